// round 2
// baseline (speedup 1.0000x reference)
#include <cuda_runtime.h>
#include <cstdint>
#include <cstddef>

#define Bsz 256
#define Tt  512
#define DIN 32
#define Hh  128
#define LATD 64
#define Gg  512   // 4*H

// Scratch (static __device__ — no allocations allowed)
__device__ float g_xg [(size_t)Bsz * Tt * Gg];   // 256 MB: x @ Wih^T + bih + bhh
__device__ float g_hs2[(size_t)Bsz * Tt * Hh];   // 64 MB : decoder hidden states

typedef unsigned long long u64;

__device__ __forceinline__ void fma2(u64& d, u64 a, u64 b) {
    asm("fma.rn.f32x2 %0, %1, %2, %0;" : "+l"(d) : "l"(a), "l"(b));
}
__device__ __forceinline__ float lo2(u64 v) { return __uint_as_float((unsigned)(v & 0xffffffffu)); }
__device__ __forceinline__ float hi2(u64 v) { return __uint_as_float((unsigned)(v >> 32)); }

__device__ __forceinline__ float sigm(float x)   { return __fdividef(1.f, 1.f + __expf(-x)); }
__device__ __forceinline__ float tanh_f(float x) { return __fdividef(2.f, 1.f + __expf(-2.f * x)) - 1.f; }

// ---------------------------------------------------------------------------
// Kernel A: g_xg[b,t,j] = sum_d x[b,t,d]*Wih[j,d] + bih[j] + bhh[j]
// grid 1024 x 512 threads; thread = gate column j; block = 128 (b,t) rows
// ---------------------------------------------------------------------------
__global__ __launch_bounds__(512) void xg_kernel(
    const float* __restrict__ x, const float* __restrict__ Wih,
    const float* __restrict__ bih, const float* __restrict__ bhh)
{
    const int j = threadIdx.x;
    const size_t row0 = (size_t)blockIdx.x * 128;
    __shared__ float xs[128 * DIN];   // 16 KB

    const float4* src = (const float4*)(x + row0 * DIN);
    float4* dst = (float4*)xs;
    for (int i = j; i < 128 * DIN / 4; i += 512) dst[i] = src[i];

    u64 w[16];
    const u64* wr = (const u64*)(Wih + j * DIN);   // 128B-aligned rows
    #pragma unroll
    for (int p = 0; p < 16; p++) w[p] = wr[p];
    float bias = __ldg(bih + j) + __ldg(bhh + j);
    __syncthreads();

    for (int r = 0; r < 128; r++) {
        u64 acc = 0;
        const u64* xp = (const u64*)(xs + r * DIN);
        #pragma unroll
        for (int p = 0; p < 16; p++) fma2(acc, w[p], xp[p]);
        g_xg[(row0 + r) * Gg + j] = lo2(acc) + hi2(acc) + bias;
    }
}

// ---------------------------------------------------------------------------
// Recurrent LSTM kernel (persistent over T). 128 CTAs x 512 threads, 2 batch
// rows per CTA. Thread j owns gate row j of Whh: k=[0,64) in 64 registers,
// k=[64,128) in smem float2 pairs. h kept in smem interleaved as
// hb[p] = (h0[2p],h0[2p+1],h1[2p],h1[2p+1]) so one LDS.128 broadcast feeds
// both rows' packed-f32x2 FMAs.
// ---------------------------------------------------------------------------
#define SMEM_BYTES (131072 + 1024 + 4096 + 512)

template<bool DEC>
__global__ __launch_bounds__(512, 1) void lstm_kernel(
    const float* __restrict__ Whh,      // [512,128]
    const float* __restrict__ Wih,      // DEC: [512,64]
    const float* __restrict__ bih, const float* __restrict__ bhh,  // DEC only
    const float* __restrict__ enc_in,   // DEC: encoded [B,64]
    const float* __restrict__ Wl,  const float* __restrict__ bl,   // ENC: enc_Wl/enc_bl
    float* __restrict__ out)            // ENC: encoded out [B,64]
{
    extern __shared__ char smem[];
    u64*    Wsm = (u64*)smem;                       // [32][512] pairs (k=64..127), 128 KB
    float4* hb  = (float4*)(smem + 131072);         // [64], 1 KB
    float*  gb  = (float*)(smem + 131072 + 1024);   // [2][512], 4 KB
    float*  xb  = gb + 1024;                        // DEC: [2][64]

    const int j  = threadIdx.x;
    const int b0 = blockIdx.x * 2;

    const float* wrow = Whh + j * Hh;
    u64 wr[32];
    #pragma unroll
    for (int p = 0; p < 32; p++) wr[p] = *(const u64*)(wrow + 2 * p);
    #pragma unroll
    for (int p = 0; p < 32; p++) Wsm[p * Gg + j] = *(const u64*)(wrow + 64 + 2 * p);
    if (j < 64) hb[j] = make_float4(0.f, 0.f, 0.f, 0.f);

    float xg0 = 0.f, xg1 = 0.f;   // DEC: t-invariant input transform
    float nx0 = 0.f, nx1 = 0.f;   // ENC: prefetch regs
    if (DEC) {
        if (j < 128) xb[j] = enc_in[b0 * LATD + j];  // [2][64] contiguous
        __syncthreads();
        float a0 = 0.f, a1 = 0.f;
        const float* wi = Wih + j * LATD;
        #pragma unroll 8
        for (int d = 0; d < LATD; d++) { float w = __ldg(wi + d); a0 += w * xb[d]; a1 += w * xb[64 + d]; }
        float bias = __ldg(bih + j) + __ldg(bhh + j);
        xg0 = a0 + bias; xg1 = a1 + bias;
    } else {
        nx0 = __ldg(g_xg + ((size_t)b0 * Tt) * Gg + j);
        nx1 = __ldg(g_xg + ((size_t)(b0 + 1) * Tt) * Gg + j);
        __syncthreads();
    }

    float c = 0.f;                 // cell state, live in threads < 256
    const int r_ = j >> 7;         // combine: row (j<256)
    const int hx = j & 127;        // combine: h index
    const int gt = j >> 7;         // gate type: 0=i 1=f 2=g 3=o

    for (int t = 0; t < Tt; t++) {
        if (!DEC) {
            xg0 = nx0; xg1 = nx1;
            if (t + 1 < Tt) {
                nx0 = __ldg(g_xg + ((size_t)b0 * Tt + t + 1) * Gg + j);
                nx1 = __ldg(g_xg + ((size_t)(b0 + 1) * Tt + t + 1) * Gg + j);
            }
        }
        u64 a0 = 0, a1 = 0;
        const ulonglong2* hp = (const ulonglong2*)hb;
        #pragma unroll
        for (int p = 0; p < 32; p++) {
            ulonglong2 h4 = hp[p];
            fma2(a0, wr[p], h4.x); fma2(a1, wr[p], h4.y);
        }
        #pragma unroll
        for (int p = 0; p < 32; p++) {
            ulonglong2 h4 = hp[32 + p];
            u64 w2 = Wsm[p * Gg + j];
            fma2(a0, w2, h4.x); fma2(a1, w2, h4.y);
        }
        float v0 = lo2(a0) + hi2(a0) + xg0;
        float v1 = lo2(a1) + hi2(a1) + xg1;
        if (gt == 2) { v0 = tanh_f(v0); v1 = tanh_f(v1); }
        else         { v0 = sigm(v0);   v1 = sigm(v1);   }
        gb[j] = v0; gb[512 + j] = v1;
        __syncthreads();
        if (j < 256) {
            float iv = gb[r_ * 512 + hx];
            float fv = gb[r_ * 512 + hx + 128];
            float gv = gb[r_ * 512 + hx + 256];
            float ov = gb[r_ * 512 + hx + 384];
            c = fv * c + iv * gv;
            float h = ov * tanh_f(c);
            ((float*)hb)[(hx >> 1) * 4 + r_ * 2 + (hx & 1)] = h;
            if (DEC) g_hs2[((size_t)(b0 + r_) * Tt + t) * Hh + hx] = h;
        }
        __syncthreads();
    }

    if (!DEC) {
        // encoded = h_last @ enc_Wl^T + enc_bl  (64 outs x 2 rows)
        if (j < 128) {
            int rr = j >> 6, l = j & 63;
            const float* wlr = Wl + l * Hh;
            const float* hbf = (const float*)hb;
            float acc = __ldg(bl + l);
            #pragma unroll 16
            for (int k = 0; k < Hh; k++)
                acc += __ldg(wlr + k) * hbf[(k >> 1) * 4 + rr * 2 + (k & 1)];
            out[(b0 + rr) * LATD + l] = acc;
        }
    }
}

// ---------------------------------------------------------------------------
// Kernel D: decoded[b,t,d] = sum_h g_hs2[b,t,h]*dec_Wl[d,h] + dec_bl[d]
// grid 2048 x 256; block = 64 rows; Wl transposed in smem; h rows broadcast.
// ---------------------------------------------------------------------------
__global__ __launch_bounds__(256) void out_kernel(
    const float* __restrict__ Wl, const float* __restrict__ bl,
    float* __restrict__ out)
{
    __shared__ float hrow[64 * 128];   // 32 KB
    __shared__ float wlT[128 * 32];    // 16 KB
    const int t = threadIdx.x;
    const size_t row0 = (size_t)blockIdx.x * 64;

    const float4* src = (const float4*)(g_hs2 + row0 * Hh);
    float4* dst = (float4*)hrow;
    for (int i = t; i < 64 * 128 / 4; i += 256) dst[i] = src[i];
    for (int i = t; i < 32 * 128; i += 256) {
        int d = i >> 7, k = i & 127;
        wlT[k * 32 + d] = Wl[i];
    }
    __syncthreads();

    const int d  = t & 31;
    const int rb = t >> 5;   // 0..7 (warp-uniform -> hrow reads broadcast)
    float bias = __ldg(bl + d);
    float acc[8];
    #pragma unroll
    for (int q = 0; q < 8; q++) acc[q] = bias;
    for (int k = 0; k < 128; k++) {
        float w = wlT[k * 32 + d];
        #pragma unroll
        for (int q = 0; q < 8; q++) acc[q] += w * hrow[(rb + q * 8) * 128 + k];
    }
    #pragma unroll
    for (int q = 0; q < 8; q++) out[(row0 + rb + q * 8) * DIN + d] = acc[q];
}

// ---------------------------------------------------------------------------
extern "C" void kernel_launch(void* const* d_in, const int* in_sizes, int n_in,
                              void* d_out, int out_size)
{
    const float* x        = (const float*)d_in[0];
    const float* enc_Wih  = (const float*)d_in[1];
    const float* enc_Whh  = (const float*)d_in[2];
    const float* enc_bih  = (const float*)d_in[3];
    const float* enc_bhh  = (const float*)d_in[4];
    const float* enc_Wl   = (const float*)d_in[5];
    const float* enc_bl   = (const float*)d_in[6];
    const float* dec_Wih  = (const float*)d_in[7];
    const float* dec_Whh  = (const float*)d_in[8];
    const float* dec_bih  = (const float*)d_in[9];
    const float* dec_bhh  = (const float*)d_in[10];
    const float* dec_Wl   = (const float*)d_in[11];
    const float* dec_bl   = (const float*)d_in[12];
    float* out = (float*)d_out;

    cudaFuncSetAttribute((const void*)lstm_kernel<false>,
                         cudaFuncAttributeMaxDynamicSharedMemorySize, SMEM_BYTES);
    cudaFuncSetAttribute((const void*)lstm_kernel<true>,
                         cudaFuncAttributeMaxDynamicSharedMemorySize, SMEM_BYTES);

    // 1) input transform for encoder
    xg_kernel<<<(Bsz * Tt) / 128, 512>>>(x, enc_Wih, enc_bih, enc_bhh);
    // 2) encoder recurrence + encoded projection (writes out[0 : 256*64))
    lstm_kernel<false><<<Bsz / 2, 512, SMEM_BYTES>>>(
        enc_Whh, nullptr, nullptr, nullptr, nullptr, enc_Wl, enc_bl, out);
    // 3) decoder recurrence (reads encoded from out, writes g_hs2)
    lstm_kernel<true><<<Bsz / 2, 512, SMEM_BYTES>>>(
        dec_Whh, dec_Wih, dec_bih, dec_bhh, out, nullptr, nullptr, nullptr);
    // 4) decoded projection (writes out[256*64 : end))
    out_kernel<<<(Bsz * Tt) / 64, 256>>>(dec_Wl, dec_bl, out + Bsz * LATD);
}

// round 4
// speedup vs baseline: 1.4525x; 1.4525x over previous
#include <cuda_runtime.h>
#include <cstdint>
#include <cstddef>

#define Bsz 256
#define Tt  512
#define DIN 32
#define Hh  128
#define LATD 64
#define Gg  512   // 4*H

// Scratch (static __device__ — no allocations allowed)
__device__ float g_xg [(size_t)Bsz * Tt * Gg];   // 256 MB: x @ Wih^T + bih + bhh
__device__ float g_hs2[(size_t)Bsz * Tt * Hh];   // 64 MB : decoder hidden states

typedef unsigned long long u64;

__device__ __forceinline__ void fma2(u64& d, u64 a, u64 b) {
    asm("fma.rn.f32x2 %0, %1, %2, %0;" : "+l"(d) : "l"(a), "l"(b));
}
__device__ __forceinline__ float lo2(u64 v) { return __uint_as_float((unsigned)(v & 0xffffffffu)); }
__device__ __forceinline__ float hi2(u64 v) { return __uint_as_float((unsigned)(v >> 32)); }

__device__ __forceinline__ float sigm(float x)   { return __fdividef(1.f, 1.f + __expf(-x)); }
__device__ __forceinline__ float tanh_f(float x) { return __fdividef(2.f, 1.f + __expf(-2.f * x)) - 1.f; }

// ---------------------------------------------------------------------------
// Kernel A: g_xg[b,t,j] = sum_d x[b,t,d]*Wih[j,d] + bih[j] + bhh[j]
// ---------------------------------------------------------------------------
__global__ __launch_bounds__(512) void xg_kernel(
    const float* __restrict__ x, const float* __restrict__ Wih,
    const float* __restrict__ bih, const float* __restrict__ bhh)
{
    const int j = threadIdx.x;
    const size_t row0 = (size_t)blockIdx.x * 128;
    __shared__ float xs[128 * DIN];   // 16 KB

    const float4* src = (const float4*)(x + row0 * DIN);
    float4* dst = (float4*)xs;
    for (int i = j; i < 128 * DIN / 4; i += 512) dst[i] = src[i];

    u64 w[16];
    const u64* wr = (const u64*)(Wih + j * DIN);
    #pragma unroll
    for (int p = 0; p < 16; p++) w[p] = wr[p];
    float bias = __ldg(bih + j) + __ldg(bhh + j);
    __syncthreads();

    for (int r = 0; r < 128; r++) {
        u64 acc = 0;
        const u64* xp = (const u64*)(xs + r * DIN);
        #pragma unroll
        for (int p = 0; p < 16; p++) fma2(acc, w[p], xp[p]);
        g_xg[(row0 + r) * Gg + j] = lo2(acc) + hi2(acc) + bias;
    }
}

// ---------------------------------------------------------------------------
// Recurrent LSTM kernel. 128 CTAs x 256 threads, 2 batch rows per CTA.
// Thread j owns gate rows j and j+256. For each row, k=[0,96) lives in
// registers (2 x 48 u64 = 192 regs), k=[96,128) in smem. h is kept in smem
// interleaved as hb[p] = (h0[2p],h0[2p+1],h1[2p],h1[2p+1]) so one LDS.128
// broadcast feeds both batch rows' packed-f32x2 FMAs.
// Per warp per step: 64 broadcast LDS.128 (h) + 16 LDS.128 (W) = 128 wf,
// matching the 2-warp/SMSP FMA floor of 1024 cyc.
// ---------------------------------------------------------------------------
#define WSMA_OFF 0
#define WSMB_OFF 32768
#define HB_OFF   65536
#define GB_OFF   66560
#define XB_OFF   70656
#define SMEM_BYTES 71680

template<bool DEC>
__global__ __launch_bounds__(256, 1) void lstm_kernel(
    const float* __restrict__ Whh,      // [512,128]
    const float* __restrict__ Wih,      // DEC: [512,64]
    const float* __restrict__ bih, const float* __restrict__ bhh,  // DEC only
    const float* __restrict__ enc_in,   // DEC: encoded [B,64]
    const float* __restrict__ Wl,  const float* __restrict__ bl,   // ENC: enc_Wl/enc_bl
    float* __restrict__ out)            // ENC: encoded out [B,64]
{
    extern __shared__ char smem[];
    ulonglong2* WsmA = (ulonglong2*)(smem + WSMA_OFF);  // [8][256] : row j,   k=96..127
    ulonglong2* WsmB = (ulonglong2*)(smem + WSMB_OFF);  // [8][256] : row j+256
    float4*     hb   = (float4*)(smem + HB_OFF);        // [64] interleaved h (2 rows x 128)
    float*      gb   = (float*)(smem + GB_OFF);         // [2][4][128] gate values
    float*      xb   = (float*)(smem + XB_OFF);         // DEC: [2][64] encoded

    const int j  = threadIdx.x;
    const int b0 = blockIdx.x * 2;

    float xgA0 = 0.f, xgA1 = 0.f, xgB0 = 0.f, xgB1 = 0.f;  // DEC: t-invariant
    float nA0 = 0.f, nA1 = 0.f, nB0 = 0.f, nB1 = 0.f;      // ENC: prefetch regs
    const float* px = nullptr;

    if (DEC) {
        if (j < 128) xb[j] = enc_in[b0 * LATD + j];
        __syncthreads();
        float a0 = 0.f, a1 = 0.f, d0 = 0.f, d1 = 0.f;
        const float* wiA = Wih + j * LATD;
        const float* wiB = Wih + (j + 256) * LATD;
        #pragma unroll 8
        for (int d = 0; d < LATD; d++) {
            float wA = __ldg(wiA + d), wB = __ldg(wiB + d);
            float x0 = xb[d], x1 = xb[64 + d];
            a0 += wA * x0; a1 += wA * x1;
            d0 += wB * x0; d1 += wB * x1;
        }
        float bA = __ldg(bih + j) + __ldg(bhh + j);
        float bB = __ldg(bih + j + 256) + __ldg(bhh + j + 256);
        xgA0 = a0 + bA; xgA1 = a1 + bA;
        xgB0 = d0 + bB; xgB1 = d1 + bB;
    } else {
        px = g_xg + (size_t)b0 * Tt * Gg + j;
        nA0 = __ldg(px);
        nA1 = __ldg(px + (size_t)Tt * Gg);
        nB0 = __ldg(px + 256);
        nB1 = __ldg(px + (size_t)Tt * Gg + 256);
    }

    // Load weights: k=[0,96) to registers, k=[96,128) to smem
    const float* wrowA = Whh + j * Hh;
    const float* wrowB = Whh + (j + 256) * Hh;
    u64 wrA[48], wrB[48];
    #pragma unroll
    for (int p = 0; p < 48; p++) wrA[p] = *(const u64*)(wrowA + 2 * p);
    #pragma unroll
    for (int p = 0; p < 48; p++) wrB[p] = *(const u64*)(wrowB + 2 * p);
    #pragma unroll
    for (int q = 0; q < 8; q++) WsmA[q * 256 + j] = *(const ulonglong2*)(wrowA + 96 + 4 * q);
    #pragma unroll
    for (int q = 0; q < 8; q++) WsmB[q * 256 + j] = *(const ulonglong2*)(wrowB + 96 + 4 * q);
    if (j < 64) hb[j] = make_float4(0.f, 0.f, 0.f, 0.f);
    __syncthreads();

    float c = 0.f;                 // cell state for (r_, hx)
    const int r_ = j >> 7;
    const int hx = j & 127;

    for (int t = 0; t < Tt; t++) {
        if (!DEC) {
            xgA0 = nA0; xgA1 = nA1; xgB0 = nB0; xgB1 = nB1;
            if (t + 1 < Tt) {
                const float* p2 = px + (size_t)(t + 1) * Gg;
                nA0 = __ldg(p2);
                nA1 = __ldg(p2 + (size_t)Tt * Gg);
                nB0 = __ldg(p2 + 256);
                nB1 = __ldg(p2 + (size_t)Tt * Gg + 256);
            }
        }
        u64 a0 = 0, a1 = 0, e0 = 0, e1 = 0;
        const ulonglong2* hp = (const ulonglong2*)hb;
        #pragma unroll
        for (int p = 0; p < 48; p++) {
            ulonglong2 h4 = hp[p];
            fma2(a0, wrA[p], h4.x); fma2(a1, wrA[p], h4.y);
            fma2(e0, wrB[p], h4.x); fma2(e1, wrB[p], h4.y);
        }
        #pragma unroll
        for (int q = 0; q < 8; q++) {
            ulonglong2 h4a = hp[48 + 2 * q];
            ulonglong2 h4b = hp[49 + 2 * q];
            ulonglong2 wa = WsmA[q * 256 + j];
            ulonglong2 wb = WsmB[q * 256 + j];
            fma2(a0, wa.x, h4a.x); fma2(a1, wa.x, h4a.y);
            fma2(a0, wa.y, h4b.x); fma2(a1, wa.y, h4b.y);
            fma2(e0, wb.x, h4a.x); fma2(e1, wb.x, h4a.y);
            fma2(e0, wb.y, h4b.x); fma2(e1, wb.y, h4b.y);
        }
        float vA0 = lo2(a0) + hi2(a0) + xgA0;   // gate row j   : i (j<128) / f
        float vA1 = lo2(a1) + hi2(a1) + xgA1;
        float vB0 = lo2(e0) + hi2(e0) + xgB0;   // gate row j+256: g (j<128) / o
        float vB1 = lo2(e1) + hi2(e1) + xgB1;
        vA0 = sigm(vA0); vA1 = sigm(vA1);
        if (j < 128) { vB0 = tanh_f(vB0); vB1 = tanh_f(vB1); }
        else         { vB0 = sigm(vB0);   vB1 = sigm(vB1);   }
        gb[j]             = vA0;  gb[512 + j]       = vA1;
        gb[256 + j]       = vB0;  gb[512 + 256 + j] = vB1;
        __syncthreads();

        // combine: thread j -> (row r_, h index hx)
        {
            const float* base = gb + r_ * 512;
            float iv = base[hx];
            float fv = base[128 + hx];
            float gv = base[256 + hx];
            float ov = base[384 + hx];
            c = fv * c + iv * gv;
            float h = ov * tanh_f(c);
            ((float*)hb)[(hx >> 1) * 4 + r_ * 2 + (hx & 1)] = h;
            if (DEC) g_hs2[((size_t)(b0 + r_) * Tt + t) * Hh + hx] = h;
        }
        __syncthreads();
    }

    if (!DEC) {
        // encoded = h_last @ enc_Wl^T + enc_bl  (64 outs x 2 rows)
        if (j < 128) {
            int rr = j >> 6, l = j & 63;
            const float* wlr = Wl + l * Hh;
            const float* hbf = (const float*)hb;
            float acc = __ldg(bl + l);
            #pragma unroll 16
            for (int k = 0; k < Hh; k++)
                acc += __ldg(wlr + k) * hbf[(k >> 1) * 4 + rr * 2 + (k & 1)];
            out[(b0 + rr) * LATD + l] = acc;
        }
    }
}

// ---------------------------------------------------------------------------
// Kernel D: decoded[b,t,d] = sum_h g_hs2[b,t,h]*dec_Wl[d,h] + dec_bl[d]
// grid 2048 x 256; block = 64 rows. Lane = d (Wl rows per-lane float4),
// h rows broadcast as float4; packed-f32x2 MACs.
// ---------------------------------------------------------------------------
__global__ __launch_bounds__(256) void out_kernel(
    const float* __restrict__ Wl, const float* __restrict__ bl,
    float* __restrict__ out)
{
    __shared__ __align__(16) float hrow[64 * 128];   // 32 KB
    __shared__ __align__(16) float wl[32 * 128];     // 4 KB  (copy of Wl, row-major)
    const int t = threadIdx.x;
    const size_t row0 = (size_t)blockIdx.x * 64;

    {
        const float4* src = (const float4*)(g_hs2 + row0 * Hh);
        float4* dst = (float4*)hrow;
        #pragma unroll
        for (int i = t; i < 64 * 128 / 4; i += 256) dst[i] = src[i];
        const float4* ws = (const float4*)Wl;
        float4* wd = (float4*)wl;
        #pragma unroll
        for (int i = t; i < 32 * 128 / 4; i += 256) wd[i] = ws[i];
    }
    __syncthreads();

    const int d  = t & 31;
    const int rb = t >> 5;   // warp-uniform -> hrow reads broadcast
    u64 acc[8];
    #pragma unroll
    for (int q = 0; q < 8; q++) acc[q] = 0;

    const ulonglong2* wl2 = (const ulonglong2*)wl + d * 32;
    const ulonglong2* h2  = (const ulonglong2*)hrow;
    #pragma unroll 4
    for (int kq = 0; kq < 32; kq++) {
        ulonglong2 w = wl2[kq];
        #pragma unroll
        for (int q = 0; q < 8; q++) {
            ulonglong2 h = h2[(rb + q * 8) * 32 + kq];
            fma2(acc[q], w.x, h.x);
            fma2(acc[q], w.y, h.y);
        }
    }
    float bias = __ldg(bl + d);
    #pragma unroll
    for (int q = 0; q < 8; q++)
        out[(row0 + rb + q * 8) * DIN + d] = lo2(acc[q]) + hi2(acc[q]) + bias;
}

// ---------------------------------------------------------------------------
extern "C" void kernel_launch(void* const* d_in, const int* in_sizes, int n_in,
                              void* d_out, int out_size)
{
    const float* x        = (const float*)d_in[0];
    const float* enc_Wih  = (const float*)d_in[1];
    const float* enc_Whh  = (const float*)d_in[2];
    const float* enc_bih  = (const float*)d_in[3];
    const float* enc_bhh  = (const float*)d_in[4];
    const float* enc_Wl   = (const float*)d_in[5];
    const float* enc_bl   = (const float*)d_in[6];
    const float* dec_Wih  = (const float*)d_in[7];
    const float* dec_Whh  = (const float*)d_in[8];
    const float* dec_bih  = (const float*)d_in[9];
    const float* dec_bhh  = (const float*)d_in[10];
    const float* dec_Wl   = (const float*)d_in[11];
    const float* dec_bl   = (const float*)d_in[12];
    float* out = (float*)d_out;

    cudaFuncSetAttribute((const void*)lstm_kernel<false>,
                         cudaFuncAttributeMaxDynamicSharedMemorySize, SMEM_BYTES);
    cudaFuncSetAttribute((const void*)lstm_kernel<true>,
                         cudaFuncAttributeMaxDynamicSharedMemorySize, SMEM_BYTES);

    // 1) input transform for encoder
    xg_kernel<<<(Bsz * Tt) / 128, 512>>>(x, enc_Wih, enc_bih, enc_bhh);
    // 2) encoder recurrence + encoded projection (writes out[0 : 256*64))
    lstm_kernel<false><<<Bsz / 2, 256, SMEM_BYTES>>>(
        enc_Whh, nullptr, nullptr, nullptr, nullptr, enc_Wl, enc_bl, out);
    // 3) decoder recurrence (reads encoded from out, writes g_hs2)
    lstm_kernel<true><<<Bsz / 2, 256, SMEM_BYTES>>>(
        dec_Whh, dec_Wih, dec_bih, dec_bhh, out, nullptr, nullptr, nullptr);
    // 4) decoded projection (writes out[256*64 : end))
    out_kernel<<<(Bsz * Tt) / 64, 256>>>(dec_Wl, dec_bl, out + Bsz * LATD);
}